// round 1
// baseline (speedup 1.0000x reference)
#include <cuda_runtime.h>
#include <cuda_bf16.h>
#include <cstdint>

// Problem constants
#define TT 2
#define NN 4096
#define DD 1024
#define EE 8
#define OO 1024
#define NTOK (TT * NN)          // 8192 tokens total

// ---------------- device scratch (static allocation only) ----------------
__device__ int   g_count[EE];
__device__ int   g_tok [EE][NTOK];
__device__ int   g_slot[EE][NTOK];
__device__ float g_gate[EE][NTOK];
// partial[slot][token][o] ; every (token,slot) written exactly once
__device__ float g_partial[2][(size_t)NTOK * OO];

// ---------------- kernel 0: zero per-expert counters ----------------
__global__ void zero_counts_kernel() {
    if (threadIdx.x < EE) g_count[threadIdx.x] = 0;
}

// ---------------- kernel 1: gating (logits -> top2 -> scatter) ----------------
// grid: NTOK/64 blocks of 256 threads; each warp handles 8 tokens sequentially.
__global__ __launch_bounds__(256) void gating_kernel(
    const float* __restrict__ x, const float* __restrict__ Wg)
{
    __shared__ float sWg[DD * EE];   // 32 KB: Wg for this block's task
    const int tok0 = blockIdx.x * 64;
    const int task = tok0 / NN;      // all 64 tokens in same task (4096 % 64 == 0)

    const float4* wg4 = (const float4*)(Wg + (size_t)task * DD * EE);
    for (int i = threadIdx.x; i < DD * EE / 4; i += 256)
        ((float4*)sWg)[i] = wg4[i];
    __syncthreads();

    const int warp = threadIdx.x >> 5;
    const int lane = threadIdx.x & 31;

    for (int j = 0; j < 8; ++j) {
        const int token = tok0 + warp * 8 + j;
        const float* xr = x + (size_t)token * DD;

        float acc[EE];
#pragma unroll
        for (int e = 0; e < EE; ++e) acc[e] = 0.0f;

        for (int d = lane; d < DD; d += 32) {
            const float xv = xr[d];
            const float4 w0 = *(const float4*)&sWg[d * EE];
            const float4 w1 = *(const float4*)&sWg[d * EE + 4];
            acc[0] += xv * w0.x; acc[1] += xv * w0.y;
            acc[2] += xv * w0.z; acc[3] += xv * w0.w;
            acc[4] += xv * w1.x; acc[5] += xv * w1.y;
            acc[6] += xv * w1.z; acc[7] += xv * w1.w;
        }
#pragma unroll
        for (int off = 16; off; off >>= 1)
#pragma unroll
            for (int e = 0; e < EE; ++e)
                acc[e] += __shfl_xor_sync(0xFFFFFFFFu, acc[e], off);

        if (lane == 0) {
            // top-1: strict > keeps earliest index (matches jax.lax.top_k)
            int e0 = 0;
#pragma unroll
            for (int e = 1; e < EE; ++e) if (acc[e] > acc[e0]) e0 = e;
            // top-2: earliest index among remaining
            int e1 = (e0 == 0) ? 1 : 0;
#pragma unroll
            for (int e = 0; e < EE; ++e)
                if (e != e0 && e != e1 && acc[e] > acc[e1]) e1 = e;

            const float denom = acc[e0] + acc[e1] + 1e-9f;
            const float gA = acc[e0] / denom;
            const float gB = acc[e1] / denom;

            int p0 = atomicAdd(&g_count[e0], 1);
            g_tok[e0][p0] = token; g_slot[e0][p0] = 0; g_gate[e0][p0] = gA;
            int p1 = atomicAdd(&g_count[e1], 1);
            g_tok[e1][p1] = token; g_slot[e1][p1] = 1; g_gate[e1][p1] = gB;
        }
    }
}

// ---------------- kernel 2: gathered per-expert SGEMM ----------------
// C[m,n] = gate[m] * sum_k x[tok[m],k] * We[e][k,n], written to g_partial[slot[m]][tok[m]][n]
#define BM 128
#define BN 128
#define BK 16

__global__ __launch_bounds__(256) void expert_gemm_kernel(
    const float* __restrict__ x, const float* __restrict__ We)
{
    const int e  = blockIdx.z;
    const int c  = g_count[e];
    const int m0 = blockIdx.y * BM;
    if (m0 >= c) return;
    const int n0 = blockIdx.x * BN;

    __shared__ float As[BK][BM];
    __shared__ float Bs[BK][BN];
    __shared__ int   stok[BM];
    __shared__ float sgate[BM];
    __shared__ int   sslot[BM];

    const int tid = threadIdx.x;
    if (tid < BM) {
        const int m = m0 + tid;
        if (m < c) {
            stok[tid]  = g_tok[e][m];
            sgate[tid] = g_gate[e][m];
            sslot[tid] = g_slot[e][m];
        } else {
            stok[tid] = 0; sgate[tid] = 0.0f; sslot[tid] = 0;
        }
    }
    __syncthreads();

    const float* Be = We + (size_t)e * DD * OO;

    // A-load mapping: 2 threads per row, 8 floats each
    const int arow = tid >> 1;
    const int acol = (tid & 1) * 8;
    const float* xrow = x + (size_t)stok[arow] * DD + acol;
    // B-load mapping: 16 threads per k-row, 8 floats each
    const int brow = tid >> 4;
    const int bcol = (tid & 15) * 8;
    // compute mapping: 8x8 per thread
    const int tx = tid & 15;
    const int ty = tid >> 4;

    float acc[8][8];
#pragma unroll
    for (int i = 0; i < 8; ++i)
#pragma unroll
        for (int j = 0; j < 8; ++j) acc[i][j] = 0.0f;

    for (int k0 = 0; k0 < DD; k0 += BK) {
        const float4 a0 = *(const float4*)(xrow + k0);
        const float4 a1 = *(const float4*)(xrow + k0 + 4);
        const float* bptr = Be + (size_t)(k0 + brow) * OO + n0 + bcol;
        const float4 b0 = *(const float4*)(bptr);
        const float4 b1 = *(const float4*)(bptr + 4);

        As[acol + 0][arow] = a0.x; As[acol + 1][arow] = a0.y;
        As[acol + 2][arow] = a0.z; As[acol + 3][arow] = a0.w;
        As[acol + 4][arow] = a1.x; As[acol + 5][arow] = a1.y;
        As[acol + 6][arow] = a1.z; As[acol + 7][arow] = a1.w;
        *(float4*)&Bs[brow][bcol]     = b0;
        *(float4*)&Bs[brow][bcol + 4] = b1;
        __syncthreads();

#pragma unroll
        for (int kk = 0; kk < BK; ++kk) {
            float a[8], b[8];
            *(float4*)(a)     = *(const float4*)&As[kk][ty * 8];
            *(float4*)(a + 4) = *(const float4*)&As[kk][ty * 8 + 4];
            *(float4*)(b)     = *(const float4*)&Bs[kk][tx * 8];
            *(float4*)(b + 4) = *(const float4*)&Bs[kk][tx * 8 + 4];
#pragma unroll
            for (int i = 0; i < 8; ++i)
#pragma unroll
                for (int j = 0; j < 8; ++j)
                    acc[i][j] += a[i] * b[j];
        }
        __syncthreads();
    }

    // epilogue: scale by gate, scatter into partial buffer
#pragma unroll
    for (int i = 0; i < 8; ++i) {
        const int m = ty * 8 + i;
        if (m0 + m < c) {
            const float g = sgate[m];
            float* dst = &g_partial[sslot[m]][(size_t)stok[m] * OO + n0 + tx * 8];
            float4 v0, v1;
            v0.x = acc[i][0] * g; v0.y = acc[i][1] * g;
            v0.z = acc[i][2] * g; v0.w = acc[i][3] * g;
            v1.x = acc[i][4] * g; v1.y = acc[i][5] * g;
            v1.z = acc[i][6] * g; v1.w = acc[i][7] * g;
            *(float4*)(dst)     = v0;
            *(float4*)(dst + 4) = v1;
        }
    }
}

// ---------------- kernel 3: combine the two slots ----------------
__global__ void combine_kernel(float* __restrict__ out) {
    const size_t i = (size_t)blockIdx.x * blockDim.x + threadIdx.x; // float4 idx
    const size_t total4 = (size_t)NTOK * OO / 4;
    if (i < total4) {
        const float4 a = ((const float4*)g_partial[0])[i];
        const float4 b = ((const float4*)g_partial[1])[i];
        float4 r;
        r.x = a.x + b.x; r.y = a.y + b.y; r.z = a.z + b.z; r.w = a.w + b.w;
        ((float4*)out)[i] = r;
    }
}

// ---------------- launch ----------------
extern "C" void kernel_launch(void* const* d_in, const int* in_sizes, int n_in,
                              void* d_out, int out_size)
{
    const float* x  = (const float*)d_in[0];   // [T, N, D]
    const float* Wg = (const float*)d_in[1];   // [T, D, E]
    const float* We = (const float*)d_in[2];   // [E, D, O]
    // d_in[3] = k (always 2 for this problem)
    float* out = (float*)d_out;                // [T, N, O]

    zero_counts_kernel<<<1, 32>>>();
    gating_kernel<<<NTOK / 64, 256>>>(x, Wg);

    dim3 grid(OO / BN, NTOK / BM, EE);  // (8, 64, 8); inactive tiles exit early
    expert_gemm_kernel<<<grid, 256>>>(x, We);

    const size_t total4 = (size_t)NTOK * OO / 4;
    combine_kernel<<<(unsigned)((total4 + 255) / 256), 256>>>(out);
}

// round 3
// speedup vs baseline: 2.2225x; 2.2225x over previous
#include <cuda_runtime.h>
#include <cuda_bf16.h>
#include <cstdint>

#define TT 2
#define NN 4096
#define DD 1024
#define EE 8
#define OO 1024
#define NTOK (TT * NN)

// GEMM tiling
#define BM 128
#define BN 128
#define BK 32
#define NCHUNK (DD / BK)      // 32
#define NTHREADS 512

// smem: header (stok 512B, sgate 512B) then 3 stages of 40960B
#define ROWB 80               // padded row stride (64B data + 16B pad) -> conflict-free ldmatrix
#define OFF_AH 0
#define OFF_AL 10240
#define OFF_BH 20480
#define OFF_BL 30720
#define STAGE_BYTES 40960
#define HDR_BYTES 1024
#define SMEM_TOTAL (HDR_BYTES + 3 * STAGE_BYTES)

// ---------------- device scratch ----------------
__device__ int   g_count[EE];
__device__ int   g_tok[EE][NTOK];
__device__ float g_gate[EE][NTOK];
__device__ __nv_bfloat16 g_xhi[(size_t)NTOK * DD];
__device__ __nv_bfloat16 g_xlo[(size_t)NTOK * DD];
__device__ __nv_bfloat16 g_whi[(size_t)EE * OO * DD];   // [e][n][k]
__device__ __nv_bfloat16 g_wlo[(size_t)EE * OO * DD];

// ---------------- PTX helpers ----------------
__device__ __forceinline__ uint32_t smem_to_u32(const void* p) {
    uint32_t a;
    asm("{ .reg .u64 t; cvta.to.shared.u64 t, %1; cvt.u32.u64 %0, t; }" : "=r"(a) : "l"(p));
    return a;
}
#define CP_ASYNC16(dst, src) \
    asm volatile("cp.async.cg.shared.global [%0], [%1], 16;" :: "r"(dst), "l"(src) : "memory")
#define CP_COMMIT() asm volatile("cp.async.commit_group;" ::: "memory")
#define CP_WAIT1()  asm volatile("cp.async.wait_group 1;" ::: "memory")
#define CP_WAIT0()  asm volatile("cp.async.wait_group 0;" ::: "memory")

#define LDSM_X4(r, addr) \
    asm volatile("ldmatrix.sync.aligned.m8n8.x4.shared.b16 {%0,%1,%2,%3}, [%4];" \
        : "=r"((r)[0]), "=r"((r)[1]), "=r"((r)[2]), "=r"((r)[3]) : "r"(addr))

#define MMA_BF16(d, a, b0, b1) \
    asm volatile("mma.sync.aligned.m16n8k16.row.col.f32.bf16.bf16.f32 " \
        "{%0,%1,%2,%3},{%4,%5,%6,%7},{%8,%9},{%0,%1,%2,%3};" \
        : "+f"((d)[0]), "+f"((d)[1]), "+f"((d)[2]), "+f"((d)[3]) \
        : "r"((a)[0]), "r"((a)[1]), "r"((a)[2]), "r"((a)[3]), "r"(b0), "r"(b1))

// ---------------- kernel 0: zero counts ----------------
__global__ void zero_counts_kernel() {
    if (threadIdx.x < EE) g_count[threadIdx.x] = 0;
}

// ---------------- kernel 1: gating ----------------
__global__ __launch_bounds__(256) void gating_kernel(
    const float* __restrict__ x, const float* __restrict__ Wg)
{
    __shared__ float sWg[DD * EE];
    const int tok0 = blockIdx.x * 64;
    const int task = tok0 / NN;

    const float4* wg4 = (const float4*)(Wg + (size_t)task * DD * EE);
    for (int i = threadIdx.x; i < DD * EE / 4; i += 256)
        ((float4*)sWg)[i] = wg4[i];
    __syncthreads();

    const int warp = threadIdx.x >> 5;
    const int lane = threadIdx.x & 31;

    for (int j = 0; j < 8; ++j) {
        const int token = tok0 + warp * 8 + j;
        const float* xr = x + (size_t)token * DD;

        float acc[EE];
#pragma unroll
        for (int e = 0; e < EE; ++e) acc[e] = 0.0f;
        for (int d = lane; d < DD; d += 32) {
            const float xv = xr[d];
            const float4 w0 = *(const float4*)&sWg[d * EE];
            const float4 w1 = *(const float4*)&sWg[d * EE + 4];
            acc[0] += xv * w0.x; acc[1] += xv * w0.y;
            acc[2] += xv * w0.z; acc[3] += xv * w0.w;
            acc[4] += xv * w1.x; acc[5] += xv * w1.y;
            acc[6] += xv * w1.z; acc[7] += xv * w1.w;
        }
#pragma unroll
        for (int off = 16; off; off >>= 1)
#pragma unroll
            for (int e = 0; e < EE; ++e)
                acc[e] += __shfl_xor_sync(0xFFFFFFFFu, acc[e], off);

        if (lane == 0) {
            int e0 = 0;
#pragma unroll
            for (int e = 1; e < EE; ++e) if (acc[e] > acc[e0]) e0 = e;
            int e1 = (e0 == 0) ? 1 : 0;
#pragma unroll
            for (int e = 0; e < EE; ++e)
                if (e != e0 && e != e1 && acc[e] > acc[e1]) e1 = e;

            const float denom = acc[e0] + acc[e1] + 1e-9f;
            int p0 = atomicAdd(&g_count[e0], 1);
            g_tok[e0][p0] = token; g_gate[e0][p0] = acc[e0] / denom;
            int p1 = atomicAdd(&g_count[e1], 1);
            g_tok[e1][p1] = token; g_gate[e1][p1] = acc[e1] / denom;
        }
    }
}

// ---------------- kernel 2: split x into bf16 hi/lo ----------------
__global__ __launch_bounds__(256) void convert_x_kernel(const float* __restrict__ x) {
    const size_t i = (size_t)blockIdx.x * 256 + threadIdx.x;   // float4 index
    const float4 v = ((const float4*)x)[i];
    __nv_bfloat16 h0 = __float2bfloat16(v.x), h1 = __float2bfloat16(v.y);
    __nv_bfloat16 h2 = __float2bfloat16(v.z), h3 = __float2bfloat16(v.w);
    __nv_bfloat16 l0 = __float2bfloat16(v.x - __bfloat162float(h0));
    __nv_bfloat16 l1 = __float2bfloat16(v.y - __bfloat162float(h1));
    __nv_bfloat16 l2 = __float2bfloat16(v.z - __bfloat162float(h2));
    __nv_bfloat16 l3 = __float2bfloat16(v.w - __bfloat162float(h3));
    __nv_bfloat162* dh = (__nv_bfloat162*)g_xhi + i * 2;
    __nv_bfloat162* dl = (__nv_bfloat162*)g_xlo + i * 2;
    dh[0] = __nv_bfloat162(h0, h1); dh[1] = __nv_bfloat162(h2, h3);
    dl[0] = __nv_bfloat162(l0, l1); dl[1] = __nv_bfloat162(l2, l3);
}

// ---------------- kernel 3: transpose + split We -> [e][n][k] hi/lo ----------------
__global__ void convert_w_kernel(const float* __restrict__ We) {
    __shared__ float tile[32][33];
    const int e  = blockIdx.z;
    const int n0 = blockIdx.x * 32;
    const int k0 = blockIdx.y * 32;
    const int tx = threadIdx.x, ty = threadIdx.y;

    for (int r = ty; r < 32; r += 8)
        tile[r][tx] = We[((size_t)e * DD + k0 + r) * OO + n0 + tx];
    __syncthreads();
    for (int r = ty; r < 32; r += 8) {
        const float v = tile[tx][r];     // = We[e][k0+tx][n0+r]
        const __nv_bfloat16 h = __float2bfloat16(v);
        const __nv_bfloat16 l = __float2bfloat16(v - __bfloat162float(h));
        const size_t o = ((size_t)e * OO + n0 + r) * DD + k0 + tx;
        g_whi[o] = h; g_wlo[o] = l;
    }
}

// ---------------- kernel 4: zero output ----------------
__global__ __launch_bounds__(256) void zero_out_kernel(float* __restrict__ out) {
    const size_t i = (size_t)blockIdx.x * 256 + threadIdx.x;
    ((float4*)out)[i] = make_float4(0.f, 0.f, 0.f, 0.f);
}

// ---------------- kernel 5: gathered expert GEMM via HMMA ----------------
__global__ __launch_bounds__(NTHREADS, 1) void expert_gemm_hmma(float* __restrict__ out)
{
    extern __shared__ char smem[];
    const int e  = blockIdx.z;
    const int c  = g_count[e];
    const int m0 = blockIdx.y * BM;
    if (m0 >= c) return;
    const int n0 = blockIdx.x * BN;

    const int tid  = threadIdx.x;
    const int lane = tid & 31;
    const int wid  = tid >> 5;
    const int mw   = wid & 3;     // warp M index (0..3) -> rows 32*mw
    const int nw   = wid >> 2;    // warp N index (0..3) -> cols 32*nw

    const uint32_t sb = smem_to_u32(smem);
    int*   stok  = (int*)smem;
    float* sgate = (float*)(smem + 512);

    if (tid < BM) {
        const int m = m0 + tid;
        if (m < c) { stok[tid] = g_tok[e][m]; sgate[tid] = g_gate[e][m]; }
        else       { stok[tid] = 0;           sgate[tid] = 0.0f; }
    }
    __syncthreads();

    // ---- per-thread cp.async mapping: row = tid>>2 (0..127), chunk = tid&3 ----
    const int ldrow = tid >> 2;
    const int ldc   = tid & 3;
    const __nv_bfloat16* srcAh = g_xhi + (size_t)stok[ldrow] * DD + ldc * 8;
    const __nv_bfloat16* srcAl = g_xlo + (size_t)stok[ldrow] * DD + ldc * 8;
    const size_t boff = ((size_t)e * OO + n0 + ldrow) * DD + ldc * 8;
    const __nv_bfloat16* srcBh = g_whi + boff;
    const __nv_bfloat16* srcBl = g_wlo + boff;
    const uint32_t dstOff = (uint32_t)(ldrow * ROWB + ldc * 16);

    // ---- prologue: chunks 0,1 ----
#pragma unroll
    for (int p = 0; p < 2; ++p) {
        const uint32_t st = sb + HDR_BYTES + p * STAGE_BYTES;
        const int k0 = p * BK;
        CP_ASYNC16(st + OFF_AH + dstOff, srcAh + k0);
        CP_ASYNC16(st + OFF_AL + dstOff, srcAl + k0);
        CP_ASYNC16(st + OFF_BH + dstOff, srcBh + k0);
        CP_ASYNC16(st + OFF_BL + dstOff, srcBl + k0);
        CP_COMMIT();
    }

    // ---- per-thread ldmatrix address bases ----
    // A: row16 = (l&7) + 8*((l>>3)&1), kchunk = l>>4
    const uint32_t aoff = (uint32_t)(OFF_AH + (32 * mw + ((lane & 7) + 8 * ((lane >> 3) & 1))) * ROWB
                                     + (lane >> 4) * 16);
    // B: nrow = (l&7) + 8*(l>>4), kchunk = (l>>3)&1
    const uint32_t boff2 = (uint32_t)(OFF_BH + (32 * nw + ((lane & 7) + 8 * (lane >> 4))) * ROWB
                                      + ((lane >> 3) & 1) * 16);

    float acc[2][4][4];
#pragma unroll
    for (int t = 0; t < 2; ++t)
#pragma unroll
        for (int j = 0; j < 4; ++j)
#pragma unroll
            for (int z = 0; z < 4; ++z) acc[t][j][z] = 0.0f;

    for (int ck = 0; ck < NCHUNK; ++ck) {
        if (ck < NCHUNK - 1) CP_WAIT1(); else CP_WAIT0();
        __syncthreads();

        // prefetch chunk ck+2
        if (ck + 2 < NCHUNK) {
            const uint32_t st = sb + HDR_BYTES + ((ck + 2) % 3) * STAGE_BYTES;
            const int k0 = (ck + 2) * BK;
            CP_ASYNC16(st + OFF_AH + dstOff, srcAh + k0);
            CP_ASYNC16(st + OFF_AL + dstOff, srcAl + k0);
            CP_ASYNC16(st + OFF_BH + dstOff, srcBh + k0);
            CP_ASYNC16(st + OFF_BL + dstOff, srcBl + k0);
            CP_COMMIT();
        }

        const uint32_t st = sb + HDR_BYTES + (ck % 3) * STAGE_BYTES;
        const uint32_t aB = st + aoff;
        const uint32_t bB = st + boff2;

#pragma unroll
        for (int q = 0; q < 2; ++q) {
            uint32_t ah[2][4], al[2][4], bh[2][4], bl[2][4];
            LDSM_X4(ah[0], aB + q * 32);
            LDSM_X4(ah[1], aB + 16 * ROWB + q * 32);
            LDSM_X4(al[0], aB + 10240 + q * 32);
            LDSM_X4(al[1], aB + 10240 + 16 * ROWB + q * 32);
            LDSM_X4(bh[0], bB + q * 32);
            LDSM_X4(bh[1], bB + 16 * ROWB + q * 32);
            LDSM_X4(bl[0], bB + 10240 + q * 32);
            LDSM_X4(bl[1], bB + 10240 + 16 * ROWB + q * 32);

#pragma unroll
            for (int t = 0; t < 2; ++t) {
#pragma unroll
                for (int g = 0; g < 2; ++g) {
                    MMA_BF16(acc[t][2 * g + 0], ah[t], bh[g][0], bh[g][1]);
                    MMA_BF16(acc[t][2 * g + 1], ah[t], bh[g][2], bh[g][3]);
                    MMA_BF16(acc[t][2 * g + 0], ah[t], bl[g][0], bl[g][1]);
                    MMA_BF16(acc[t][2 * g + 1], ah[t], bl[g][2], bl[g][3]);
                    MMA_BF16(acc[t][2 * g + 0], al[t], bh[g][0], bh[g][1]);
                    MMA_BF16(acc[t][2 * g + 1], al[t], bh[g][2], bh[g][3]);
                }
            }
        }
    }

    // ---- epilogue: gate scale + atomic combine ----
#pragma unroll
    for (int t = 0; t < 2; ++t) {
#pragma unroll
        for (int h = 0; h < 2; ++h) {            // c pair half (rows +0 / +8)
            const int r = 32 * mw + 16 * t + (lane >> 2) + 8 * h;
            if (m0 + r < c) {
                const float g   = sgate[r];
                float* obase = out + (size_t)stok[r] * OO + n0 + 32 * nw + 2 * (lane & 3);
#pragma unroll
                for (int j = 0; j < 4; ++j) {
                    atomicAdd(obase + 8 * j,     g * acc[t][j][2 * h + 0]);
                    atomicAdd(obase + 8 * j + 1, g * acc[t][j][2 * h + 1]);
                }
            }
        }
    }
}

// ---------------- launch ----------------
extern "C" void kernel_launch(void* const* d_in, const int* in_sizes, int n_in,
                              void* d_out, int out_size)
{
    const float* x  = (const float*)d_in[0];   // [T, N, D]
    const float* Wg = (const float*)d_in[1];   // [T, D, E]
    const float* We = (const float*)d_in[2];   // [E, D, O]
    float* out = (float*)d_out;                // [T, N, O]

    zero_counts_kernel<<<1, 32>>>();
    gating_kernel<<<NTOK / 64, 256>>>(x, Wg);
    convert_x_kernel<<<(NTOK * DD / 4) / 256, 256>>>(x);
    {
        dim3 g(OO / 32, DD / 32, EE), b(32, 8);
        convert_w_kernel<<<g, b>>>(We);
    }
    zero_out_kernel<<<(NTOK * OO / 4) / 256, 256>>>(out);

    cudaFuncSetAttribute(expert_gemm_hmma, cudaFuncAttributeMaxDynamicSharedMemorySize, SMEM_TOTAL);
    dim3 grid(OO / BN, NTOK / BM, EE);   // (8, 64, 8); inactive tiles exit early
    expert_gemm_hmma<<<grid, NTHREADS, SMEM_TOTAL>>>(out);
}

// round 4
// speedup vs baseline: 2.2995x; 1.0346x over previous
#include <cuda_runtime.h>
#include <cuda_bf16.h>
#include <cstdint>

#define TT 2
#define NN 4096
#define DD 1024
#define EE 8
#define OO 1024
#define NTOK (TT * NN)

// GEMM tiling
#define BM 128
#define BN 128
#define BK 64
#define NCHUNK (DD / BK)      // 16
#define NTHREADS 512

// smem stage: rows padded to 144B (128B data + 16B) -> conflict-free ldmatrix
#define ROWB 144
#define OFF_AL 18432          // 128 * 144
#define OFF_BH 36864
#define OFF_BL 55296
#define STAGE_BYTES 73728
#define HDR_BYTES 2048
#define NSTAGE 3
#define SMEM_TOTAL (HDR_BYTES + NSTAGE * STAGE_BYTES)   // 223232

// ---------------- device scratch ----------------
__device__ int   g_count[EE];
__device__ int   g_tok[EE][NTOK];
__device__ int   g_slot[EE][NTOK];
__device__ float g_gate[EE][NTOK];
__device__ __nv_bfloat16 g_xhi[(size_t)NTOK * DD];
__device__ __nv_bfloat16 g_xlo[(size_t)NTOK * DD];
__device__ __nv_bfloat16 g_whi[(size_t)EE * OO * DD];   // [e][n][k]
__device__ __nv_bfloat16 g_wlo[(size_t)EE * OO * DD];
__device__ float g_partial[2][(size_t)NTOK * OO];       // [slot][token][o]

// ---------------- PTX helpers ----------------
__device__ __forceinline__ uint32_t smem_to_u32(const void* p) {
    uint32_t a;
    asm("{ .reg .u64 t; cvta.to.shared.u64 t, %1; cvt.u32.u64 %0, t; }" : "=r"(a) : "l"(p));
    return a;
}
#define CP_ASYNC16(dst, src) \
    asm volatile("cp.async.cg.shared.global [%0], [%1], 16;" :: "r"(dst), "l"(src) : "memory")
#define CP_COMMIT() asm volatile("cp.async.commit_group;" ::: "memory")
#define CP_WAIT1()  asm volatile("cp.async.wait_group 1;" ::: "memory")
#define CP_WAIT0()  asm volatile("cp.async.wait_group 0;" ::: "memory")

#define LDSM_X4(r, addr) \
    asm volatile("ldmatrix.sync.aligned.m8n8.x4.shared.b16 {%0,%1,%2,%3}, [%4];" \
        : "=r"((r)[0]), "=r"((r)[1]), "=r"((r)[2]), "=r"((r)[3]) : "r"(addr))

#define MMA_BF16(d, a, b0, b1) \
    asm volatile("mma.sync.aligned.m16n8k16.row.col.f32.bf16.bf16.f32 " \
        "{%0,%1,%2,%3},{%4,%5,%6,%7},{%8,%9},{%0,%1,%2,%3};" \
        : "+f"((d)[0]), "+f"((d)[1]), "+f"((d)[2]), "+f"((d)[3]) \
        : "r"((a)[0]), "r"((a)[1]), "r"((a)[2]), "r"((a)[3]), "r"(b0), "r"(b1))

// ---------------- kernel 0: zero counts ----------------
__global__ void zero_counts_kernel() {
    if (threadIdx.x < EE) g_count[threadIdx.x] = 0;
}

// ---------------- kernel 1: fused gating + x hi/lo split (single x read) ----------------
__global__ __launch_bounds__(256) void gating_split_kernel(
    const float* __restrict__ x, const float* __restrict__ Wg)
{
    __shared__ float sWg[DD * EE];   // 32 KB
    const int tok0 = blockIdx.x * 64;
    const int task = tok0 / NN;

    const float4* wg4 = (const float4*)(Wg + (size_t)task * DD * EE);
    for (int i = threadIdx.x; i < DD * EE / 4; i += 256)
        ((float4*)sWg)[i] = wg4[i];
    __syncthreads();

    const int warp = threadIdx.x >> 5;
    const int lane = threadIdx.x & 31;

    for (int j = 0; j < 8; ++j) {
        const int token = tok0 + warp * 8 + j;
        const float4* x4 = (const float4*)(x + (size_t)token * DD);

        float acc[EE];
#pragma unroll
        for (int e = 0; e < EE; ++e) acc[e] = 0.0f;

#pragma unroll
        for (int i = 0; i < 8; ++i) {
            const int idx = i * 32 + lane;      // float4 index within row
            const float4 v = x4[idx];
            const int d0 = idx * 4;
            const float* vp = &v.x;
#pragma unroll
            for (int m = 0; m < 4; ++m) {
                const float xv = vp[m];
                const float4 w0 = *(const float4*)&sWg[(d0 + m) * EE];
                const float4 w1 = *(const float4*)&sWg[(d0 + m) * EE + 4];
                acc[0] += xv * w0.x; acc[1] += xv * w0.y;
                acc[2] += xv * w0.z; acc[3] += xv * w0.w;
                acc[4] += xv * w1.x; acc[5] += xv * w1.y;
                acc[6] += xv * w1.z; acc[7] += xv * w1.w;
            }
            // split hi/lo and store (8B per lane, coalesced 256B/warp)
            __nv_bfloat16 h0 = __float2bfloat16(v.x), h1 = __float2bfloat16(v.y);
            __nv_bfloat16 h2 = __float2bfloat16(v.z), h3 = __float2bfloat16(v.w);
            __nv_bfloat16 l0 = __float2bfloat16(v.x - __bfloat162float(h0));
            __nv_bfloat16 l1 = __float2bfloat16(v.y - __bfloat162float(h1));
            __nv_bfloat16 l2 = __float2bfloat16(v.z - __bfloat162float(h2));
            __nv_bfloat16 l3 = __float2bfloat16(v.w - __bfloat162float(h3));
            __nv_bfloat162 ha(h0, h1), hb(h2, h3), la(l0, l1), lb(l2, l3);
            uint2 hu = make_uint2(*(uint32_t*)&ha, *(uint32_t*)&hb);
            uint2 lu = make_uint2(*(uint32_t*)&la, *(uint32_t*)&lb);
            *(uint2*)(g_xhi + (size_t)token * DD + d0) = hu;
            *(uint2*)(g_xlo + (size_t)token * DD + d0) = lu;
        }

#pragma unroll
        for (int off = 16; off; off >>= 1)
#pragma unroll
            for (int e = 0; e < EE; ++e)
                acc[e] += __shfl_xor_sync(0xFFFFFFFFu, acc[e], off);

        if (lane == 0) {
            int e0 = 0;
#pragma unroll
            for (int e = 1; e < EE; ++e) if (acc[e] > acc[e0]) e0 = e;
            int e1 = (e0 == 0) ? 1 : 0;
#pragma unroll
            for (int e = 0; e < EE; ++e)
                if (e != e0 && e != e1 && acc[e] > acc[e1]) e1 = e;

            const float denom = acc[e0] + acc[e1] + 1e-9f;
            int p0 = atomicAdd(&g_count[e0], 1);
            g_tok[e0][p0] = token; g_slot[e0][p0] = 0; g_gate[e0][p0] = acc[e0] / denom;
            int p1 = atomicAdd(&g_count[e1], 1);
            g_tok[e1][p1] = token; g_slot[e1][p1] = 1; g_gate[e1][p1] = acc[e1] / denom;
        }
    }
}

// ---------------- kernel 2: transpose + split We -> [e][n][k] hi/lo ----------------
// tile 64(k) x 32(n); writes paired-k 4B stores, fully coalesced
__global__ void convert_w_kernel(const float* __restrict__ We) {
    __shared__ float tile[64][33];
    const int e  = blockIdx.z;
    const int n0 = blockIdx.x * 32;
    const int k0 = blockIdx.y * 64;
    const int tx = threadIdx.x, ty = threadIdx.y;

    for (int r = ty; r < 64; r += 8)
        tile[r][tx] = We[((size_t)e * DD + k0 + r) * OO + n0 + tx];
    __syncthreads();
#pragma unroll
    for (int s = 0; s < 4; ++s) {
        const int n = s * 8 + ty;
        const float v0 = tile[2 * tx][n];
        const float v1 = tile[2 * tx + 1][n];
        const __nv_bfloat16 h0 = __float2bfloat16(v0);
        const __nv_bfloat16 h1 = __float2bfloat16(v1);
        const __nv_bfloat16 l0 = __float2bfloat16(v0 - __bfloat162float(h0));
        const __nv_bfloat16 l1 = __float2bfloat16(v1 - __bfloat162float(h1));
        __nv_bfloat162 hp(h0, h1), lp(l0, l1);
        const size_t o = ((size_t)e * OO + n0 + n) * DD + k0 + 2 * tx;
        *(__nv_bfloat162*)(g_whi + o) = hp;
        *(__nv_bfloat162*)(g_wlo + o) = lp;
    }
}

// ---------------- kernel 3: gathered expert GEMM via HMMA ----------------
__device__ __forceinline__ void load_stage(uint32_t st, int k0, int e, int n0,
                                           const int* stok, int tid)
{
#pragma unroll
    for (int i = tid; i < 1024; i += NTHREADS) {
        const int row = i >> 3, c = i & 7;
        const uint32_t dst = st + (uint32_t)(row * ROWB + c * 16);
        const size_t asrc = (size_t)stok[row] * DD + k0 + c * 8;
        CP_ASYNC16(dst,          g_xhi + asrc);
        CP_ASYNC16(dst + OFF_AL, g_xlo + asrc);
        const size_t bsrc = ((size_t)e * OO + n0 + row) * DD + k0 + c * 8;
        CP_ASYNC16(dst + OFF_BH, g_whi + bsrc);
        CP_ASYNC16(dst + OFF_BL, g_wlo + bsrc);
    }
    CP_COMMIT();
}

__global__ __launch_bounds__(NTHREADS, 1) void expert_gemm_hmma()
{
    extern __shared__ char smem[];
    const int e  = blockIdx.z;
    const int c  = g_count[e];
    const int m0 = blockIdx.y * BM;
    if (m0 >= c) return;
    const int n0 = blockIdx.x * BN;

    const int tid  = threadIdx.x;
    const int lane = tid & 31;
    const int wid  = tid >> 5;
    const int mw   = wid & 3;
    const int nw   = wid >> 2;

    const uint32_t sb = smem_to_u32(smem);
    int*   stok  = (int*)smem;
    float* sgate = (float*)(smem + 512);
    int*   sslot = (int*)(smem + 1024);

    if (tid < BM) {
        const int m = m0 + tid;
        if (m < c) { stok[tid] = g_tok[e][m]; sgate[tid] = g_gate[e][m]; sslot[tid] = g_slot[e][m]; }
        else       { stok[tid] = 0;           sgate[tid] = 0.0f;         sslot[tid] = 0; }
    }
    __syncthreads();

    const uint32_t stage0 = sb + HDR_BYTES;
    // prologue: chunks 0,1
    load_stage(stage0,               0,  e, n0, stok, tid);
    load_stage(stage0 + STAGE_BYTES, BK, e, n0, stok, tid);

    // ldmatrix per-thread bases (within a stage)
    const uint32_t aoff = (uint32_t)((32 * mw + ((lane & 7) + 8 * ((lane >> 3) & 1))) * ROWB
                                     + (lane >> 4) * 16);
    const uint32_t boff = (uint32_t)(OFF_BH + (32 * nw + ((lane & 7) + 8 * (lane >> 4))) * ROWB
                                     + ((lane >> 3) & 1) * 16);

    float acc[2][4][4];
#pragma unroll
    for (int t = 0; t < 2; ++t)
#pragma unroll
        for (int j = 0; j < 4; ++j)
#pragma unroll
            for (int z = 0; z < 4; ++z) acc[t][j][z] = 0.0f;

    uint32_t Ah[2][2][4], Al[2][2][4], Bh[2][2][4], Bl[2][2][4];

#define LOADQ(buf, st, q) do { \
    LDSM_X4(Ah[buf][0], (st) + aoff + (q) * 32); \
    LDSM_X4(Ah[buf][1], (st) + aoff + 16 * ROWB + (q) * 32); \
    LDSM_X4(Al[buf][0], (st) + aoff + OFF_AL + (q) * 32); \
    LDSM_X4(Al[buf][1], (st) + aoff + OFF_AL + 16 * ROWB + (q) * 32); \
    LDSM_X4(Bh[buf][0], (st) + boff + (q) * 32); \
    LDSM_X4(Bh[buf][1], (st) + boff + 16 * ROWB + (q) * 32); \
    LDSM_X4(Bl[buf][0], (st) + boff + 18432 + (q) * 32); \
    LDSM_X4(Bl[buf][1], (st) + boff + 18432 + 16 * ROWB + (q) * 32); \
} while (0)

#define MMAQ(buf) do { \
    _Pragma("unroll") \
    for (int t = 0; t < 2; ++t) { \
        _Pragma("unroll") \
        for (int g = 0; g < 2; ++g) { \
            MMA_BF16(acc[t][2 * g + 0], Ah[buf][t], Bh[buf][g][0], Bh[buf][g][1]); \
            MMA_BF16(acc[t][2 * g + 1], Ah[buf][t], Bh[buf][g][2], Bh[buf][g][3]); \
            MMA_BF16(acc[t][2 * g + 0], Ah[buf][t], Bl[buf][g][0], Bl[buf][g][1]); \
            MMA_BF16(acc[t][2 * g + 1], Ah[buf][t], Bl[buf][g][2], Bl[buf][g][3]); \
            MMA_BF16(acc[t][2 * g + 0], Al[buf][t], Bh[buf][g][0], Bh[buf][g][1]); \
            MMA_BF16(acc[t][2 * g + 1], Al[buf][t], Bh[buf][g][2], Bh[buf][g][3]); \
        } \
    } \
} while (0)

    for (int ck = 0; ck < NCHUNK; ++ck) {
        if (ck < NCHUNK - 1) CP_WAIT1(); else CP_WAIT0();
        __syncthreads();

        if (ck + 2 < NCHUNK)
            load_stage(stage0 + ((ck + 2) % NSTAGE) * STAGE_BYTES, (ck + 2) * BK, e, n0, stok, tid);

        const uint32_t st = stage0 + (ck % NSTAGE) * STAGE_BYTES;
        LOADQ(0, st, 0);
#pragma unroll
        for (int q = 0; q < 4; ++q) {
            if (q < 3) {
                if ((q & 1) == 0) LOADQ(1, st, q + 1);
                else              LOADQ(0, st, q + 1);
            }
            if ((q & 1) == 0) MMAQ(0); else MMAQ(1);
        }
    }

    // ---- epilogue: restage C through smem, plain vector stores to slot partials ----
    __syncthreads();
    float* sC = (float*)(smem + HDR_BYTES);   // 128 rows x stride 136 floats
#pragma unroll
    for (int t = 0; t < 2; ++t) {
#pragma unroll
        for (int h = 0; h < 2; ++h) {
            const int r = 32 * mw + 16 * t + (lane >> 2) + 8 * h;
#pragma unroll
            for (int j = 0; j < 4; ++j) {
                const int col = 32 * nw + 8 * j + 2 * (lane & 3);
                float2 v = make_float2(acc[t][j][2 * h], acc[t][j][2 * h + 1]);
                *(float2*)&sC[r * 136 + col] = v;
            }
        }
    }
    __syncthreads();

#pragma unroll
    for (int rr = 0; rr < 8; ++rr) {
        const int row = wid * 8 + rr;
        if (m0 + row < c) {
            const float g = sgate[row];
            const float* src = &sC[row * 136 + lane * 4];
            float4 v = make_float4(src[0] * g, src[1] * g, src[2] * g, src[3] * g);
            float* dst = g_partial[sslot[row]] + (size_t)stok[row] * OO + n0 + lane * 4;
            *(float4*)dst = v;
        }
    }
}

// ---------------- kernel 4: combine the two slots ----------------
__global__ __launch_bounds__(256) void combine_kernel(float* __restrict__ out) {
    const size_t i = (size_t)blockIdx.x * 256 + threadIdx.x;
    const float4 a = ((const float4*)g_partial[0])[i];
    const float4 b = ((const float4*)g_partial[1])[i];
    float4 r;
    r.x = a.x + b.x; r.y = a.y + b.y; r.z = a.z + b.z; r.w = a.w + b.w;
    ((float4*)out)[i] = r;
}

// ---------------- launch ----------------
extern "C" void kernel_launch(void* const* d_in, const int* in_sizes, int n_in,
                              void* d_out, int out_size)
{
    const float* x  = (const float*)d_in[0];   // [T, N, D]
    const float* Wg = (const float*)d_in[1];   // [T, D, E]
    const float* We = (const float*)d_in[2];   // [E, D, O]
    float* out = (float*)d_out;                // [T, N, O]

    zero_counts_kernel<<<1, 32>>>();
    gating_split_kernel<<<NTOK / 64, 256>>>(x, Wg);
    {
        dim3 g(OO / 32, DD / 64, EE), b(32, 8);
        convert_w_kernel<<<g, b>>>(We);
    }

    cudaFuncSetAttribute(expert_gemm_hmma, cudaFuncAttributeMaxDynamicSharedMemorySize, SMEM_TOTAL);
    dim3 grid(OO / BN, NTOK / BM, EE);   // (8, 64, 8); inactive tiles exit early
    expert_gemm_hmma<<<grid, NTHREADS, SMEM_TOTAL>>>();

    combine_kernel<<<(NTOK * OO / 4) / 256, 256>>>(out);
}

// round 5
// speedup vs baseline: 2.6706x; 1.1614x over previous
#include <cuda_runtime.h>
#include <cuda_bf16.h>
#include <cstdint>

#define TT 2
#define NN 4096
#define DD 1024
#define EE 8
#define OO 1024
#define NTOK (TT * NN)

// GEMM tiling: CTA 128x256, 16 warps of 32x64, BK=32, tf32 single pass
#define BM 128
#define BN 256
#define BK 32
#define NCHUNK (DD / BK)       // 32
#define NTHREADS 512

#define ROWW 36                // words per smem row (32 data + 4 pad); 36%32==4 -> conflict-free frags
#define ROWB 144
#define OFF_B 18432            // A region = 128*144
#define STAGE_BYTES 55296      // A 18432 + B 36864
#define STAGE_WORDS (STAGE_BYTES / 4)
#define NSTAGE 4
#define HDR_BYTES 2048
#define SMEM_TOTAL (HDR_BYTES + NSTAGE * STAGE_BYTES)   // 223232

// ---------------- device scratch ----------------
__device__ int      g_count[EE];
__device__ int      g_tok[EE][NTOK];
__device__ int      g_slot[EE][NTOK];
__device__ float    g_gate[EE][NTOK];
__device__ uint32_t g_xt[(size_t)NTOK * DD];            // tf32-rounded x  [token][k]
__device__ uint32_t g_wt[(size_t)EE * OO * DD];         // tf32-rounded We^T [e][n][k]
__device__ float    g_partial[2][(size_t)NTOK * OO];    // [slot][token][o]

// ---------------- PTX helpers ----------------
__device__ __forceinline__ uint32_t cvt_tf32(float v) {
    uint32_t r;
    asm("cvt.rna.tf32.f32 %0, %1;" : "=r"(r) : "f"(v));
    return r;
}
#define CP_ASYNC16(dst, src) \
    asm volatile("cp.async.cg.shared.global [%0], [%1], 16;" :: "r"(dst), "l"(src) : "memory")
#define CP_COMMIT() asm volatile("cp.async.commit_group;" ::: "memory")
#define CP_WAIT2()  asm volatile("cp.async.wait_group 2;" ::: "memory")
#define CP_WAIT1()  asm volatile("cp.async.wait_group 1;" ::: "memory")
#define CP_WAIT0()  asm volatile("cp.async.wait_group 0;" ::: "memory")

__device__ __forceinline__ uint32_t smem_to_u32(const void* p) {
    uint32_t a;
    asm("{ .reg .u64 t; cvta.to.shared.u64 t, %1; cvt.u32.u64 %0, t; }" : "=r"(a) : "l"(p));
    return a;
}

#define MMA_TF32(d, a, b0, b1) \
    asm volatile("mma.sync.aligned.m16n8k8.row.col.f32.tf32.tf32.f32 " \
        "{%0,%1,%2,%3},{%4,%5,%6,%7},{%8,%9},{%0,%1,%2,%3};" \
        : "+f"((d)[0]), "+f"((d)[1]), "+f"((d)[2]), "+f"((d)[3]) \
        : "r"((a)[0]), "r"((a)[1]), "r"((a)[2]), "r"((a)[3]), "r"(b0), "r"(b1))

// ---------------- kernel 0: zero counts ----------------
__global__ void zero_counts_kernel() {
    if (threadIdx.x < EE) g_count[threadIdx.x] = 0;
}

// ---------------- kernel 1: fused gating + tf32 rounding of x ----------------
__global__ __launch_bounds__(256) void gating_round_kernel(
    const float* __restrict__ x, const float* __restrict__ Wg)
{
    __shared__ float sWg[DD * EE];
    const int tok0 = blockIdx.x * 64;
    const int task = tok0 / NN;

    const float4* wg4 = (const float4*)(Wg + (size_t)task * DD * EE);
    for (int i = threadIdx.x; i < DD * EE / 4; i += 256)
        ((float4*)sWg)[i] = wg4[i];
    __syncthreads();

    const int warp = threadIdx.x >> 5;
    const int lane = threadIdx.x & 31;

    for (int j = 0; j < 8; ++j) {
        const int token = tok0 + warp * 8 + j;
        const float4* x4 = (const float4*)(x + (size_t)token * DD);

        float acc[EE];
#pragma unroll
        for (int e = 0; e < EE; ++e) acc[e] = 0.0f;

#pragma unroll
        for (int i = 0; i < 8; ++i) {
            const int idx = i * 32 + lane;
            const float4 v = x4[idx];
            const int d0 = idx * 4;
            const float* vp = &v.x;
#pragma unroll
            for (int m = 0; m < 4; ++m) {
                const float xv = vp[m];
                const float4 w0 = *(const float4*)&sWg[(d0 + m) * EE];
                const float4 w1 = *(const float4*)&sWg[(d0 + m) * EE + 4];
                acc[0] += xv * w0.x; acc[1] += xv * w0.y;
                acc[2] += xv * w0.z; acc[3] += xv * w0.w;
                acc[4] += xv * w1.x; acc[5] += xv * w1.y;
                acc[6] += xv * w1.z; acc[7] += xv * w1.w;
            }
            uint4 t;
            t.x = cvt_tf32(v.x); t.y = cvt_tf32(v.y);
            t.z = cvt_tf32(v.z); t.w = cvt_tf32(v.w);
            *(uint4*)(g_xt + (size_t)token * DD + d0) = t;
        }

#pragma unroll
        for (int off = 16; off; off >>= 1)
#pragma unroll
            for (int e = 0; e < EE; ++e)
                acc[e] += __shfl_xor_sync(0xFFFFFFFFu, acc[e], off);

        if (lane == 0) {
            int e0 = 0;
#pragma unroll
            for (int e = 1; e < EE; ++e) if (acc[e] > acc[e0]) e0 = e;
            int e1 = (e0 == 0) ? 1 : 0;
#pragma unroll
            for (int e = 0; e < EE; ++e)
                if (e != e0 && e != e1 && acc[e] > acc[e1]) e1 = e;

            const float denom = acc[e0] + acc[e1] + 1e-9f;
            int p0 = atomicAdd(&g_count[e0], 1);
            g_tok[e0][p0] = token; g_slot[e0][p0] = 0; g_gate[e0][p0] = acc[e0] / denom;
            int p1 = atomicAdd(&g_count[e1], 1);
            g_tok[e1][p1] = token; g_slot[e1][p1] = 1; g_gate[e1][p1] = acc[e1] / denom;
        }
    }
}

// ---------------- kernel 2: transpose + tf32 round We -> [e][n][k] ----------------
__global__ void convert_w_kernel(const float* __restrict__ We) {
    __shared__ float tile[64][33];
    const int e  = blockIdx.z;
    const int n0 = blockIdx.x * 32;
    const int k0 = blockIdx.y * 64;
    const int tx = threadIdx.x, ty = threadIdx.y;

    for (int r = ty; r < 64; r += 8)
        tile[r][tx] = We[((size_t)e * DD + k0 + r) * OO + n0 + tx];
    __syncthreads();
#pragma unroll
    for (int s = 0; s < 4; ++s) {
        const int n = s * 8 + ty;
        uint2 p;
        p.x = cvt_tf32(tile[2 * tx][n]);
        p.y = cvt_tf32(tile[2 * tx + 1][n]);
        *(uint2*)(g_wt + ((size_t)e * OO + n0 + n) * DD + k0 + 2 * tx) = p;
    }
}

// ---------------- kernel 3: gathered expert GEMM, tf32 HMMA ----------------
__device__ __forceinline__ void load_stage(uint32_t st, int k0, int e, int n0,
                                           const int* stok, int tid)
{
    // A: 128 rows x 128B
#pragma unroll
    for (int i = tid; i < 1024; i += NTHREADS) {
        const int row = i >> 3, cc = i & 7;
        CP_ASYNC16(st + (uint32_t)(row * ROWB + cc * 16),
                   g_xt + (size_t)stok[row] * DD + k0 + cc * 4);
    }
    // B: 256 rows x 128B
    const size_t bbase = ((size_t)e * OO + n0) * DD + k0;
#pragma unroll
    for (int i = tid; i < 2048; i += NTHREADS) {
        const int row = i >> 3, cc = i & 7;
        CP_ASYNC16(st + OFF_B + (uint32_t)(row * ROWB + cc * 16),
                   g_wt + bbase + (size_t)row * DD + cc * 4);
    }
    CP_COMMIT();
}

__global__ __launch_bounds__(NTHREADS, 1) void expert_gemm_tf32()
{
    extern __shared__ char smem[];
    const int e  = blockIdx.z;
    const int c  = g_count[e];
    const int m0 = blockIdx.y * BM;
    if (m0 >= c) return;
    const int n0 = blockIdx.x * BN;

    const int tid  = threadIdx.x;
    const int lane = tid & 31;
    const int wid  = tid >> 5;
    const int mw   = wid & 3;      // 4 m-warps, 32 rows each
    const int nw   = wid >> 2;     // 4 n-warps, 64 cols each
    const int grp  = lane >> 2;    // 0..7
    const int thr  = lane & 3;     // 0..3

    const uint32_t sb = smem_to_u32(smem);
    int*   stok  = (int*)smem;
    float* sgate = (float*)(smem + 512);
    int*   sslot = (int*)(smem + 1024);

    if (tid < BM) {
        const int m = m0 + tid;
        if (m < c) { stok[tid] = g_tok[e][m]; sgate[tid] = g_gate[e][m]; sslot[tid] = g_slot[e][m]; }
        else       { stok[tid] = 0;           sgate[tid] = 0.0f;         sslot[tid] = 0; }
    }
    __syncthreads();

    const uint32_t stage0 = sb + HDR_BYTES;
    // prologue: 3 stages
    load_stage(stage0,                   0,      e, n0, stok, tid);
    load_stage(stage0 + STAGE_BYTES,     BK,     e, n0, stok, tid);
    load_stage(stage0 + 2 * STAGE_BYTES, 2 * BK, e, n0, stok, tid);

    // per-warp fragment base offsets (in words, within a stage)
    const uint32_t* smemw = (const uint32_t*)(smem + HDR_BYTES);
    const int aBase = (32 * mw + grp) * ROWW + thr;
    const int bBase = OFF_B / 4 + (64 * nw + grp) * ROWW + thr;

    float acc[2][8][4];
#pragma unroll
    for (int t = 0; t < 2; ++t)
#pragma unroll
        for (int j = 0; j < 8; ++j)
#pragma unroll
            for (int z = 0; z < 4; ++z) acc[t][j][z] = 0.0f;

    for (int ck = 0; ck < NCHUNK; ++ck) {
        if (ck < 30) CP_WAIT2(); else if (ck == 30) CP_WAIT1(); else CP_WAIT0();
        __syncthreads();

        if (ck + 3 < NCHUNK)
            load_stage(stage0 + ((ck + 3) & 3) * STAGE_BYTES, (ck + 3) * BK, e, n0, stok, tid);

        const uint32_t* sw = smemw + (ck & 3) * STAGE_WORDS;
        const uint32_t* aP = sw + aBase;
        const uint32_t* bP = sw + bBase;

#pragma unroll
        for (int ks = 0; ks < 4; ++ks) {
            const int kw = ks * 8;
            uint32_t a[2][4], b[8][2];
#pragma unroll
            for (int t = 0; t < 2; ++t) {
                a[t][0] = aP[(16 * t    ) * ROWW + kw];
                a[t][1] = aP[(16 * t + 8) * ROWW + kw];
                a[t][2] = aP[(16 * t    ) * ROWW + kw + 4];
                a[t][3] = aP[(16 * t + 8) * ROWW + kw + 4];
            }
#pragma unroll
            for (int j = 0; j < 8; ++j) {
                b[j][0] = bP[(8 * j) * ROWW + kw];
                b[j][1] = bP[(8 * j) * ROWW + kw + 4];
            }
#pragma unroll
            for (int t = 0; t < 2; ++t)
#pragma unroll
                for (int j = 0; j < 8; ++j)
                    MMA_TF32(acc[t][j], a[t], b[j][0], b[j][1]);
        }
    }

    // ---- epilogue: restage C through smem, plain stores to slot partials ----
    __syncthreads();
    float* sC = (float*)(smem + HDR_BYTES);   // 128 rows x stride 260 floats (133 KB)
#pragma unroll
    for (int t = 0; t < 2; ++t) {
#pragma unroll
        for (int h = 0; h < 2; ++h) {
            const int r = 32 * mw + 16 * t + grp + 8 * h;
#pragma unroll
            for (int j = 0; j < 8; ++j) {
                float2 v = make_float2(acc[t][j][2 * h], acc[t][j][2 * h + 1]);
                *(float2*)&sC[r * 260 + 64 * nw + 8 * j + 2 * thr] = v;
            }
        }
    }
    __syncthreads();

#pragma unroll
    for (int rr = 0; rr < 8; ++rr) {
        const int row = wid * 8 + rr;
        if (m0 + row < c) {
            const float g = sgate[row];
            float* dst = g_partial[sslot[row]] + (size_t)stok[row] * OO + n0;
#pragma unroll
            for (int half = 0; half < 2; ++half) {
                const float* src = &sC[row * 260 + half * 128 + lane * 4];
                float4 v = make_float4(src[0] * g, src[1] * g, src[2] * g, src[3] * g);
                *(float4*)(dst + half * 128 + lane * 4) = v;
            }
        }
    }
}

// ---------------- kernel 4: combine the two slots ----------------
__global__ __launch_bounds__(256) void combine_kernel(float* __restrict__ out) {
    const size_t i = (size_t)blockIdx.x * 256 + threadIdx.x;
    const float4 a = ((const float4*)g_partial[0])[i];
    const float4 b = ((const float4*)g_partial[1])[i];
    float4 r;
    r.x = a.x + b.x; r.y = a.y + b.y; r.z = a.z + b.z; r.w = a.w + b.w;
    ((float4*)out)[i] = r;
}

// ---------------- launch ----------------
extern "C" void kernel_launch(void* const* d_in, const int* in_sizes, int n_in,
                              void* d_out, int out_size)
{
    const float* x  = (const float*)d_in[0];   // [T, N, D]
    const float* Wg = (const float*)d_in[1];   // [T, D, E]
    const float* We = (const float*)d_in[2];   // [E, D, O]
    float* out = (float*)d_out;                // [T, N, O]

    zero_counts_kernel<<<1, 32>>>();
    gating_round_kernel<<<NTOK / 64, 256>>>(x, Wg);
    {
        dim3 g(OO / 32, DD / 64, EE), b(32, 8);
        convert_w_kernel<<<g, b>>>(We);
    }

    cudaFuncSetAttribute(expert_gemm_tf32, cudaFuncAttributeMaxDynamicSharedMemorySize, SMEM_TOTAL);
    dim3 grid(OO / BN, NTOK / BM, EE);   // (4, 64, 8); inactive tiles exit early
    expert_gemm_tf32<<<grid, NTHREADS, SMEM_TOTAL>>>();

    combine_kernel<<<(NTOK * OO / 4) / 256, 256>>>(out);
}

// round 6
// speedup vs baseline: 2.9021x; 1.0867x over previous
#include <cuda_runtime.h>
#include <cuda_bf16.h>
#include <cstdint>

#define TT 2
#define NN 4096
#define DD 1024
#define EE 8
#define OO 1024
#define NTOK (TT * NN)

// GEMM tiling: CTA 128x256, 16 warps of 32x64, BK=32, tf32 single pass
#define BM 128
#define BN 256
#define BK 32
#define NCHUNK (DD / BK)       // 32
#define NTHREADS 512

#define ROWB 144               // bytes per smem row (128 data + 16 pad)
#define OFF_B 18432            // A region = 128*144
#define STAGE_BYTES 55296
#define NSTAGE 4
#define HDR_BYTES 2048
#define SMEM_TOTAL (HDR_BYTES + NSTAGE * STAGE_BYTES)   // 223232

// ---------------- device scratch ----------------
__device__ int      g_count[EE];
__device__ int      g_tok[EE][NTOK];
__device__ int      g_slot[EE][NTOK];
__device__ float    g_gate[EE][NTOK];
__device__ uint32_t g_xt[(size_t)NTOK * DD];            // tf32-rounded x  [token][k]
__device__ uint32_t g_wt[(size_t)EE * OO * DD];         // tf32-rounded We^T [e][n][k]
__device__ float    g_partial[2][(size_t)NTOK * OO];    // [slot][token][o]

// ---------------- PTX helpers ----------------
__device__ __forceinline__ uint32_t cvt_tf32(float v) {
    uint32_t r;
    asm("cvt.rna.tf32.f32 %0, %1;" : "=r"(r) : "f"(v));
    return r;
}
#define CP_ASYNC16(dst, src) \
    asm volatile("cp.async.cg.shared.global [%0], [%1], 16;" :: "r"(dst), "l"(src) : "memory")
#define CP_COMMIT() asm volatile("cp.async.commit_group;" ::: "memory")
#define CP_WAIT2()  asm volatile("cp.async.wait_group 2;" ::: "memory")
#define CP_WAIT1()  asm volatile("cp.async.wait_group 1;" ::: "memory")
#define CP_WAIT0()  asm volatile("cp.async.wait_group 0;" ::: "memory")

__device__ __forceinline__ uint32_t smem_to_u32(const void* p) {
    uint32_t a;
    asm("{ .reg .u64 t; cvta.to.shared.u64 t, %1; cvt.u32.u64 %0, t; }" : "=r"(a) : "l"(p));
    return a;
}

#define LDSM_X4(r, addr) \
    asm volatile("ldmatrix.sync.aligned.m8n8.x4.shared.b16 {%0,%1,%2,%3}, [%4];" \
        : "=r"((r)[0]), "=r"((r)[1]), "=r"((r)[2]), "=r"((r)[3]) : "r"(addr))

#define MMA_TF32(d, a, b0, b1) \
    asm volatile("mma.sync.aligned.m16n8k8.row.col.f32.tf32.tf32.f32 " \
        "{%0,%1,%2,%3},{%4,%5,%6,%7},{%8,%9},{%0,%1,%2,%3};" \
        : "+f"((d)[0]), "+f"((d)[1]), "+f"((d)[2]), "+f"((d)[3]) \
        : "r"((a)[0]), "r"((a)[1]), "r"((a)[2]), "r"((a)[3]), "r"(b0), "r"(b1))

// ---------------- kernel 0: zero counts ----------------
__global__ void zero_counts_kernel() {
    if (threadIdx.x < EE) g_count[threadIdx.x] = 0;
}

// ---------------- kernel 1: fused gating + tf32 rounding of x ----------------
__global__ __launch_bounds__(256) void gating_round_kernel(
    const float* __restrict__ x, const float* __restrict__ Wg)
{
    __shared__ float sWg[DD * EE];
    const int tok0 = blockIdx.x * 64;
    const int task = tok0 / NN;

    const float4* wg4 = (const float4*)(Wg + (size_t)task * DD * EE);
    for (int i = threadIdx.x; i < DD * EE / 4; i += 256)
        ((float4*)sWg)[i] = wg4[i];
    __syncthreads();

    const int warp = threadIdx.x >> 5;
    const int lane = threadIdx.x & 31;

    for (int j = 0; j < 8; ++j) {
        const int token = tok0 + warp * 8 + j;
        const float4* x4 = (const float4*)(x + (size_t)token * DD);

        float acc[EE];
#pragma unroll
        for (int e = 0; e < EE; ++e) acc[e] = 0.0f;

#pragma unroll
        for (int i = 0; i < 8; ++i) {
            const int idx = i * 32 + lane;
            const float4 v = x4[idx];
            const int d0 = idx * 4;
            const float* vp = &v.x;
#pragma unroll
            for (int m = 0; m < 4; ++m) {
                const float xv = vp[m];
                const float4 w0 = *(const float4*)&sWg[(d0 + m) * EE];
                const float4 w1 = *(const float4*)&sWg[(d0 + m) * EE + 4];
                acc[0] += xv * w0.x; acc[1] += xv * w0.y;
                acc[2] += xv * w0.z; acc[3] += xv * w0.w;
                acc[4] += xv * w1.x; acc[5] += xv * w1.y;
                acc[6] += xv * w1.z; acc[7] += xv * w1.w;
            }
            uint4 t;
            t.x = cvt_tf32(v.x); t.y = cvt_tf32(v.y);
            t.z = cvt_tf32(v.z); t.w = cvt_tf32(v.w);
            *(uint4*)(g_xt + (size_t)token * DD + d0) = t;
        }

#pragma unroll
        for (int off = 16; off; off >>= 1)
#pragma unroll
            for (int e = 0; e < EE; ++e)
                acc[e] += __shfl_xor_sync(0xFFFFFFFFu, acc[e], off);

        if (lane == 0) {
            int e0 = 0;
#pragma unroll
            for (int e = 1; e < EE; ++e) if (acc[e] > acc[e0]) e0 = e;
            int e1 = (e0 == 0) ? 1 : 0;
#pragma unroll
            for (int e = 0; e < EE; ++e)
                if (e != e0 && e != e1 && acc[e] > acc[e1]) e1 = e;

            const float denom = acc[e0] + acc[e1] + 1e-9f;
            int p0 = atomicAdd(&g_count[e0], 1);
            g_tok[e0][p0] = token; g_slot[e0][p0] = 0; g_gate[e0][p0] = acc[e0] / denom;
            int p1 = atomicAdd(&g_count[e1], 1);
            g_tok[e1][p1] = token; g_slot[e1][p1] = 1; g_gate[e1][p1] = acc[e1] / denom;
        }
    }
}

// ---------------- kernel 2: transpose + tf32 round We -> [e][n][k] ----------------
__global__ void convert_w_kernel(const float* __restrict__ We) {
    __shared__ float tile[64][33];
    const int e  = blockIdx.z;
    const int n0 = blockIdx.x * 32;
    const int k0 = blockIdx.y * 64;
    const int tx = threadIdx.x, ty = threadIdx.y;

    for (int r = ty; r < 64; r += 8)
        tile[r][tx] = We[((size_t)e * DD + k0 + r) * OO + n0 + tx];
    __syncthreads();
#pragma unroll
    for (int s = 0; s < 4; ++s) {
        const int n = s * 8 + ty;
        uint2 p;
        p.x = cvt_tf32(tile[2 * tx][n]);
        p.y = cvt_tf32(tile[2 * tx + 1][n]);
        *(uint2*)(g_wt + ((size_t)e * OO + n0 + n) * DD + k0 + 2 * tx) = p;
    }
}

// ---------------- kernel 3: gathered expert GEMM, tf32 HMMA + ldmatrix ----------------
__device__ __forceinline__ void load_stage(uint32_t st, int k0, int e, int n0,
                                           const int* stok, int tid)
{
#pragma unroll
    for (int i = tid; i < 1024; i += NTHREADS) {
        const int row = i >> 3, cc = i & 7;
        CP_ASYNC16(st + (uint32_t)(row * ROWB + cc * 16),
                   g_xt + (size_t)stok[row] * DD + k0 + cc * 4);
    }
    const size_t bbase = ((size_t)e * OO + n0) * DD + k0;
#pragma unroll
    for (int i = tid; i < 2048; i += NTHREADS) {
        const int row = i >> 3, cc = i & 7;
        CP_ASYNC16(st + OFF_B + (uint32_t)(row * ROWB + cc * 16),
                   g_wt + bbase + (size_t)row * DD + cc * 4);
    }
    CP_COMMIT();
}

__global__ __launch_bounds__(NTHREADS, 1) void expert_gemm_tf32()
{
    extern __shared__ char smem[];
    const int e  = blockIdx.z;
    const int c  = g_count[e];
    const int m0 = blockIdx.y * BM;
    if (m0 >= c) return;
    const int n0 = blockIdx.x * BN;

    const int tid  = threadIdx.x;
    const int lane = tid & 31;
    const int wid  = tid >> 5;
    const int mw   = wid & 3;      // 4 m-warps, 32 rows each
    const int nw   = wid >> 2;     // 4 n-warps, 64 cols each
    const int grp  = lane >> 2;
    const int thr  = lane & 3;

    const uint32_t sb = smem_to_u32(smem);
    int*   stok  = (int*)smem;
    float* sgate = (float*)(smem + 512);
    int*   sslot = (int*)(smem + 1024);

    if (tid < BM) {
        const int m = m0 + tid;
        if (m < c) { stok[tid] = g_tok[e][m]; sgate[tid] = g_gate[e][m]; sslot[tid] = g_slot[e][m]; }
        else       { stok[tid] = 0;           sgate[tid] = 0.0f;         sslot[tid] = 0; }
    }
    __syncthreads();

    const uint32_t stage0 = sb + HDR_BYTES;
    load_stage(stage0,                   0,      e, n0, stok, tid);
    load_stage(stage0 + STAGE_BYTES,     BK,     e, n0, stok, tid);
    load_stage(stage0 + 2 * STAGE_BYTES, 2 * BK, e, n0, stok, tid);

    // ldmatrix per-lane base addresses (within stage 0)
    // A x4: M0 rows+0 col kw | M1 rows+8 col kw | M2 rows+0 col kw+4 | M3 rows+8 col kw+4
    const uint32_t aBase = stage0
        + (uint32_t)((32 * mw + (lane & 7) + 8 * ((lane >> 3) & 1)) * ROWB)
        + (uint32_t)((lane >> 4) * 16);
    // B x4: M0 n+0 col kw | M1 n+0 col kw+4 | M2 n+8 col kw | M3 n+8 col kw+4
    const uint32_t bBase = stage0 + OFF_B
        + (uint32_t)((64 * nw + (lane & 7) + 8 * (lane >> 4)) * ROWB)
        + (uint32_t)(((lane >> 3) & 1) * 16);

    float acc[2][8][4];
#pragma unroll
    for (int t = 0; t < 2; ++t)
#pragma unroll
        for (int j = 0; j < 8; ++j)
#pragma unroll
            for (int z = 0; z < 4; ++z) acc[t][j][z] = 0.0f;

    for (int ck = 0; ck < NCHUNK; ++ck) {
        if (ck < 30) CP_WAIT2(); else if (ck == 30) CP_WAIT1(); else CP_WAIT0();
        __syncthreads();

        if (ck + 3 < NCHUNK)
            load_stage(stage0 + ((ck + 3) & 3) * STAGE_BYTES, (ck + 3) * BK, e, n0, stok, tid);

        const uint32_t soff = (uint32_t)((ck & 3) * STAGE_BYTES);
        const uint32_t aB = aBase + soff;
        const uint32_t bB = bBase + soff;

#pragma unroll
        for (int ks = 0; ks < 4; ++ks) {
            const uint32_t kb = (uint32_t)(ks * 32);   // kw*4 bytes
            uint32_t a[2][4], b[8][2];
            LDSM_X4(a[0], aB + kb);
            LDSM_X4(a[1], aB + 16 * ROWB + kb);
            // b[j][0..1] pairs: one LDSM.x4 covers tiles j, j+1
#pragma unroll
            for (int jj = 0; jj < 4; ++jj) {
                uint32_t r[4];
                LDSM_X4(r, bB + (uint32_t)(jj * 16 * ROWB) + kb);
                b[2 * jj][0]     = r[0]; b[2 * jj][1]     = r[1];
                b[2 * jj + 1][0] = r[2]; b[2 * jj + 1][1] = r[3];
            }
#pragma unroll
            for (int t = 0; t < 2; ++t)
#pragma unroll
                for (int j = 0; j < 8; ++j)
                    MMA_TF32(acc[t][j], a[t], b[j][0], b[j][1]);
        }
    }

    // ---- epilogue: restage C through smem, plain stores to slot partials ----
    __syncthreads();
    float* sC = (float*)(smem + HDR_BYTES);   // 128 rows x stride 260 floats
#pragma unroll
    for (int t = 0; t < 2; ++t) {
#pragma unroll
        for (int h = 0; h < 2; ++h) {
            const int r = 32 * mw + 16 * t + grp + 8 * h;
#pragma unroll
            for (int j = 0; j < 8; ++j) {
                float2 v = make_float2(acc[t][j][2 * h], acc[t][j][2 * h + 1]);
                *(float2*)&sC[r * 260 + 64 * nw + 8 * j + 2 * thr] = v;
            }
        }
    }
    __syncthreads();

#pragma unroll
    for (int rr = 0; rr < 8; ++rr) {
        const int row = wid * 8 + rr;
        if (m0 + row < c) {
            const float g = sgate[row];
            float* dst = g_partial[sslot[row]] + (size_t)stok[row] * OO + n0;
#pragma unroll
            for (int half = 0; half < 2; ++half) {
                const float* src = &sC[row * 260 + half * 128 + lane * 4];
                float4 v = make_float4(src[0] * g, src[1] * g, src[2] * g, src[3] * g);
                *(float4*)(dst + half * 128 + lane * 4) = v;
            }
        }
    }
}

// ---------------- kernel 4: combine the two slots ----------------
__global__ __launch_bounds__(256) void combine_kernel(float* __restrict__ out) {
    const size_t i = (size_t)blockIdx.x * 256 + threadIdx.x;
    const float4 a = ((const float4*)g_partial[0])[i];
    const float4 b = ((const float4*)g_partial[1])[i];
    float4 r;
    r.x = a.x + b.x; r.y = a.y + b.y; r.z = a.z + b.z; r.w = a.w + b.w;
    ((float4*)out)[i] = r;
}

// ---------------- launch ----------------
extern "C" void kernel_launch(void* const* d_in, const int* in_sizes, int n_in,
                              void* d_out, int out_size)
{
    const float* x  = (const float*)d_in[0];   // [T, N, D]
    const float* Wg = (const float*)d_in[1];   // [T, D, E]
    const float* We = (const float*)d_in[2];   // [E, D, O]
    float* out = (float*)d_out;                // [T, N, O]

    zero_counts_kernel<<<1, 32>>>();
    gating_round_kernel<<<NTOK / 64, 256>>>(x, Wg);
    {
        dim3 g(OO / 32, DD / 64, EE), b(32, 8);
        convert_w_kernel<<<g, b>>>(We);
    }

    cudaFuncSetAttribute(expert_gemm_tf32, cudaFuncAttributeMaxDynamicSharedMemorySize, SMEM_TOTAL);
    dim3 grid(OO / BN, NTOK / BM, EE);   // (4, 64, 8); inactive tiles exit early
    expert_gemm_tf32<<<grid, NTHREADS, SMEM_TOTAL>>>();

    combine_kernel<<<(NTOK * OO / 4) / 256, 256>>>(out);
}

// round 7
// speedup vs baseline: 3.2840x; 1.1316x over previous
#include <cuda_runtime.h>
#include <cuda_bf16.h>
#include <cstdint>

#define TT 2
#define NN 4096
#define DD 1024
#define EE 8
#define OO 1024
#define NTOK (TT * NN)

// GEMM tiling: CTA 128x128, 8 warps of 32x64, BK=32, tf32 single pass, 2 CTAs/SM
#define BM 128
#define BN 128
#define BK 32
#define NCHUNK (DD / BK)       // 32
#define NTHREADS 256

#define ROWB 144               // bytes per smem row (128 data + 16 pad); 36 words % 32 == 4 -> conflict-free
#define OFF_B 18432            // A region = 128*144
#define STAGE_BYTES 36864      // A + B
#define NSTAGE 3
#define HDR_BYTES 2048
#define SMEM_TOTAL (HDR_BYTES + NSTAGE * STAGE_BYTES)   // 112640 -> 2 CTAs/SM

// ---------------- device scratch ----------------
__device__ int      g_count[EE];
__device__ int      g_tok[EE][NTOK];
__device__ int      g_slot[EE][NTOK];
__device__ float    g_gate[EE][NTOK];
__device__ uint32_t g_xt[(size_t)NTOK * DD];            // tf32-rounded x  [token][k]
__device__ uint32_t g_wt[(size_t)EE * OO * DD];         // tf32-rounded We^T [e][n][k]
__device__ float    g_partial[2][(size_t)NTOK * OO];    // [slot][token][o]

// ---------------- PTX helpers ----------------
__device__ __forceinline__ uint32_t cvt_tf32(float v) {
    uint32_t r;
    asm("cvt.rna.tf32.f32 %0, %1;" : "=r"(r) : "f"(v));
    return r;
}
#define CP_ASYNC16(dst, src) \
    asm volatile("cp.async.cg.shared.global [%0], [%1], 16;" :: "r"(dst), "l"(src) : "memory")
#define CP_COMMIT() asm volatile("cp.async.commit_group;" ::: "memory")
#define CP_WAIT1()  asm volatile("cp.async.wait_group 1;" ::: "memory")
#define CP_WAIT0()  asm volatile("cp.async.wait_group 0;" ::: "memory")

__device__ __forceinline__ uint32_t smem_to_u32(const void* p) {
    uint32_t a;
    asm("{ .reg .u64 t; cvta.to.shared.u64 t, %1; cvt.u32.u64 %0, t; }" : "=r"(a) : "l"(p));
    return a;
}

#define LDSM_X4(r, addr) \
    asm volatile("ldmatrix.sync.aligned.m8n8.x4.shared.b16 {%0,%1,%2,%3}, [%4];" \
        : "=r"((r)[0]), "=r"((r)[1]), "=r"((r)[2]), "=r"((r)[3]) : "r"(addr))

#define MMA_TF32(d, a, b0, b1) \
    asm volatile("mma.sync.aligned.m16n8k8.row.col.f32.tf32.tf32.f32 " \
        "{%0,%1,%2,%3},{%4,%5,%6,%7},{%8,%9},{%0,%1,%2,%3};" \
        : "+f"((d)[0]), "+f"((d)[1]), "+f"((d)[2]), "+f"((d)[3]) \
        : "r"((a)[0]), "r"((a)[1]), "r"((a)[2]), "r"((a)[3]), "r"(b0), "r"(b1))

// ---------------- kernel 0: zero counts ----------------
__global__ void zero_counts_kernel() {
    if (threadIdx.x < EE) g_count[threadIdx.x] = 0;
}

// ---------------- kernel 1: fused gating + tf32 rounding of x ----------------
__global__ __launch_bounds__(256) void gating_round_kernel(
    const float* __restrict__ x, const float* __restrict__ Wg)
{
    __shared__ float sWg[DD * EE];
    const int tok0 = blockIdx.x * 64;
    const int task = tok0 / NN;

    const float4* wg4 = (const float4*)(Wg + (size_t)task * DD * EE);
    for (int i = threadIdx.x; i < DD * EE / 4; i += 256)
        ((float4*)sWg)[i] = wg4[i];
    __syncthreads();

    const int warp = threadIdx.x >> 5;
    const int lane = threadIdx.x & 31;

    for (int j = 0; j < 8; ++j) {
        const int token = tok0 + warp * 8 + j;
        const float4* x4 = (const float4*)(x + (size_t)token * DD);

        float acc[EE];
#pragma unroll
        for (int e = 0; e < EE; ++e) acc[e] = 0.0f;

#pragma unroll
        for (int i = 0; i < 8; ++i) {
            const int idx = i * 32 + lane;
            const float4 v = x4[idx];
            const int d0 = idx * 4;
            const float* vp = &v.x;
#pragma unroll
            for (int m = 0; m < 4; ++m) {
                const float xv = vp[m];
                const float4 w0 = *(const float4*)&sWg[(d0 + m) * EE];
                const float4 w1 = *(const float4*)&sWg[(d0 + m) * EE + 4];
                acc[0] += xv * w0.x; acc[1] += xv * w0.y;
                acc[2] += xv * w0.z; acc[3] += xv * w0.w;
                acc[4] += xv * w1.x; acc[5] += xv * w1.y;
                acc[6] += xv * w1.z; acc[7] += xv * w1.w;
            }
            uint4 t;
            t.x = cvt_tf32(v.x); t.y = cvt_tf32(v.y);
            t.z = cvt_tf32(v.z); t.w = cvt_tf32(v.w);
            *(uint4*)(g_xt + (size_t)token * DD + d0) = t;
        }

#pragma unroll
        for (int off = 16; off; off >>= 1)
#pragma unroll
            for (int e = 0; e < EE; ++e)
                acc[e] += __shfl_xor_sync(0xFFFFFFFFu, acc[e], off);

        if (lane == 0) {
            int e0 = 0;
#pragma unroll
            for (int e = 1; e < EE; ++e) if (acc[e] > acc[e0]) e0 = e;
            int e1 = (e0 == 0) ? 1 : 0;
#pragma unroll
            for (int e = 0; e < EE; ++e)
                if (e != e0 && e != e1 && acc[e] > acc[e1]) e1 = e;

            const float denom = acc[e0] + acc[e1] + 1e-9f;
            int p0 = atomicAdd(&g_count[e0], 1);
            g_tok[e0][p0] = token; g_slot[e0][p0] = 0; g_gate[e0][p0] = acc[e0] / denom;
            int p1 = atomicAdd(&g_count[e1], 1);
            g_tok[e1][p1] = token; g_slot[e1][p1] = 1; g_gate[e1][p1] = acc[e1] / denom;
        }
    }
}

// ---------------- kernel 2: transpose + tf32 round We -> [e][n][k] ----------------
__global__ void convert_w_kernel(const float* __restrict__ We) {
    __shared__ float tile[64][33];
    const int e  = blockIdx.z;
    const int n0 = blockIdx.x * 32;
    const int k0 = blockIdx.y * 64;
    const int tx = threadIdx.x, ty = threadIdx.y;

    for (int r = ty; r < 64; r += 8)
        tile[r][tx] = We[((size_t)e * DD + k0 + r) * OO + n0 + tx];
    __syncthreads();
#pragma unroll
    for (int s = 0; s < 4; ++s) {
        const int n = s * 8 + ty;
        uint2 p;
        p.x = cvt_tf32(tile[2 * tx][n]);
        p.y = cvt_tf32(tile[2 * tx + 1][n]);
        *(uint2*)(g_wt + ((size_t)e * OO + n0 + n) * DD + k0 + 2 * tx) = p;
    }
}

// ---------------- kernel 3: gathered expert GEMM, tf32 HMMA + ldmatrix ----------------
__device__ __forceinline__ void load_stage(uint32_t st, int k0, int e, int n0,
                                           const int* stok, int tid)
{
    // A: 128 rows x 128B
#pragma unroll
    for (int i = tid; i < 1024; i += NTHREADS) {
        const int row = i >> 3, cc = i & 7;
        CP_ASYNC16(st + (uint32_t)(row * ROWB + cc * 16),
                   g_xt + (size_t)stok[row] * DD + k0 + cc * 4);
    }
    // B: 128 rows x 128B
    const size_t bbase = ((size_t)e * OO + n0) * DD + k0;
#pragma unroll
    for (int i = tid; i < 1024; i += NTHREADS) {
        const int row = i >> 3, cc = i & 7;
        CP_ASYNC16(st + OFF_B + (uint32_t)(row * ROWB + cc * 16),
                   g_wt + bbase + (size_t)row * DD + cc * 4);
    }
    CP_COMMIT();
}

__global__ __launch_bounds__(NTHREADS, 2) void expert_gemm_tf32()
{
    extern __shared__ char smem[];
    const int e  = blockIdx.z;
    const int c  = g_count[e];
    const int m0 = blockIdx.y * BM;
    if (m0 >= c) return;
    const int n0 = blockIdx.x * BN;

    const int tid  = threadIdx.x;
    const int lane = tid & 31;
    const int wid  = tid >> 5;
    const int mw   = wid & 3;      // 4 m-warps, 32 rows each
    const int nw   = wid >> 2;     // 2 n-warps, 64 cols each
    const int grp  = lane >> 2;
    const int thr  = lane & 3;

    const uint32_t sb = smem_to_u32(smem);
    int*   stok  = (int*)smem;
    float* sgate = (float*)(smem + 512);
    int*   sslot = (int*)(smem + 1024);

    if (tid < BM) {
        const int m = m0 + tid;
        if (m < c) { stok[tid] = g_tok[e][m]; sgate[tid] = g_gate[e][m]; sslot[tid] = g_slot[e][m]; }
        else       { stok[tid] = 0;           sgate[tid] = 0.0f;         sslot[tid] = 0; }
    }
    __syncthreads();

    const uint32_t stage0 = sb + HDR_BYTES;
    load_stage(stage0,               0,  e, n0, stok, tid);
    load_stage(stage0 + STAGE_BYTES, BK, e, n0, stok, tid);

    // ldmatrix per-lane base addresses (within stage 0)
    const uint32_t aBase = stage0
        + (uint32_t)((32 * mw + (lane & 7) + 8 * ((lane >> 3) & 1)) * ROWB)
        + (uint32_t)((lane >> 4) * 16);
    const uint32_t bBase = stage0 + OFF_B
        + (uint32_t)((64 * nw + (lane & 7) + 8 * (lane >> 4)) * ROWB)
        + (uint32_t)(((lane >> 3) & 1) * 16);

    float acc[2][8][4];
#pragma unroll
    for (int t = 0; t < 2; ++t)
#pragma unroll
        for (int j = 0; j < 8; ++j)
#pragma unroll
            for (int z = 0; z < 4; ++z) acc[t][j][z] = 0.0f;

    uint32_t soff = 0;                       // (ck % 3) * STAGE_BYTES
    for (int ck = 0; ck < NCHUNK; ++ck) {
        if (ck < NCHUNK - 1) CP_WAIT1(); else CP_WAIT0();
        __syncthreads();

        // load ck+2 into the slot freed by ck-1 (all warps past ck-1's reads)
        if (ck + 2 < NCHUNK) {
            uint32_t s2 = soff + 2 * STAGE_BYTES;
            if (s2 >= (uint32_t)(NSTAGE * STAGE_BYTES)) s2 -= NSTAGE * STAGE_BYTES;
            load_stage(stage0 + s2, (ck + 2) * BK, e, n0, stok, tid);
        }

        const uint32_t aB = aBase + soff;
        const uint32_t bB = bBase + soff;

#pragma unroll
        for (int ks = 0; ks < 4; ++ks) {
            const uint32_t kb = (uint32_t)(ks * 32);
            uint32_t a[2][4], b[8][2];
            LDSM_X4(a[0], aB + kb);
            LDSM_X4(a[1], aB + 16 * ROWB + kb);
#pragma unroll
            for (int jj = 0; jj < 4; ++jj) {
                uint32_t r[4];
                LDSM_X4(r, bB + (uint32_t)(jj * 16 * ROWB) + kb);
                b[2 * jj][0]     = r[0]; b[2 * jj][1]     = r[1];
                b[2 * jj + 1][0] = r[2]; b[2 * jj + 1][1] = r[3];
            }
#pragma unroll
            for (int t = 0; t < 2; ++t)
#pragma unroll
                for (int j = 0; j < 8; ++j)
                    MMA_TF32(acc[t][j], a[t], b[j][0], b[j][1]);
        }

        soff += STAGE_BYTES;
        if (soff >= (uint32_t)(NSTAGE * STAGE_BYTES)) soff = 0;
    }

    // ---- epilogue: restage C through smem, plain stores to slot partials ----
    __syncthreads();
    float* sC = (float*)(smem + HDR_BYTES);   // 128 rows x stride 132 floats (67.5 KB)
#pragma unroll
    for (int t = 0; t < 2; ++t) {
#pragma unroll
        for (int h = 0; h < 2; ++h) {
            const int r = 32 * mw + 16 * t + grp + 8 * h;
#pragma unroll
            for (int j = 0; j < 8; ++j) {
                float2 v = make_float2(acc[t][j][2 * h], acc[t][j][2 * h + 1]);
                *(float2*)&sC[r * 132 + 64 * nw + 8 * j + 2 * thr] = v;
            }
        }
    }
    __syncthreads();

#pragma unroll
    for (int rr = 0; rr < 16; ++rr) {
        const int row = wid * 16 + rr;
        if (m0 + row < c) {
            const float g = sgate[row];
            const float* src = &sC[row * 132 + lane * 4];
            float4 v = make_float4(src[0] * g, src[1] * g, src[2] * g, src[3] * g);
            float* dst = g_partial[sslot[row]] + (size_t)stok[row] * OO + n0 + lane * 4;
            *(float4*)dst = v;
        }
    }
}

// ---------------- kernel 4: combine the two slots ----------------
__global__ __launch_bounds__(256) void combine_kernel(float* __restrict__ out) {
    const size_t i = (size_t)blockIdx.x * 256 + threadIdx.x;
    const float4 a = ((const float4*)g_partial[0])[i];
    const float4 b = ((const float4*)g_partial[1])[i];
    float4 r;
    r.x = a.x + b.x; r.y = a.y + b.y; r.z = a.z + b.z; r.w = a.w + b.w;
    ((float4*)out)[i] = r;
}

// ---------------- launch ----------------
extern "C" void kernel_launch(void* const* d_in, const int* in_sizes, int n_in,
                              void* d_out, int out_size)
{
    const float* x  = (const float*)d_in[0];   // [T, N, D]
    const float* Wg = (const float*)d_in[1];   // [T, D, E]
    const float* We = (const float*)d_in[2];   // [E, D, O]
    float* out = (float*)d_out;                // [T, N, O]

    zero_counts_kernel<<<1, 32>>>();
    gating_round_kernel<<<NTOK / 64, 256>>>(x, Wg);
    {
        dim3 g(OO / 32, DD / 64, EE), b(32, 8);
        convert_w_kernel<<<g, b>>>(We);
    }

    cudaFuncSetAttribute(expert_gemm_tf32, cudaFuncAttributeMaxDynamicSharedMemorySize, SMEM_TOTAL);
    dim3 grid(OO / BN, NTOK / BM, EE);   // (8, 64, 8); inactive tiles exit early
    expert_gemm_tf32<<<grid, NTHREADS, SMEM_TOTAL>>>();

    combine_kernel<<<(NTOK * OO / 4) / 256, 256>>>(out);
}